// round 15
// baseline (speedup 1.0000x reference)
#include <cuda_runtime.h>

// Problem constants
#define B_    4
#define T_    16
#define C_    256
#define H_    64
#define W_    64
#define HEADS 8
#define DH    32          // head dim
#define NSEQ  (B_*T_*H_)  // 4096 sequences of length W_=64
#define NTOK  (NSEQ*W_)   // 262144 tokens
#define SCALE 0.17677669529663689f  // 1/sqrt(32)

// Scratch: the exact footprint that passes (delta 0).
// g_q is reused for the attention output.
__device__ float g_q[(size_t)NTOK * C_];
__device__ float g_k[(size_t)NTOK * C_];
__device__ float g_v[(size_t)NTOK * C_];

// ---------------------------------------------------------------------------
// Packed f32x2 helpers (PTX 8.6, baseline sm_100): one instr = 2 fp32 FMAs.
// ptxas never emits FFMA2 from C++; it is reachable only via PTX f32x2 ops.
// ---------------------------------------------------------------------------
#define FMA2(d, a, b) \
    asm("fma.rn.f32x2 %0, %1, %2, %0;" : "+l"(d) : "l"(a), "l"(b))
#define ADD2(d, a, b) \
    asm("add.rn.f32x2 %0, %1, %2;" : "=l"(d) : "l"(a), "l"(b))
#define PACK2(d, s) \
    asm("mov.b64 %0, {%1, %1};" : "=l"(d) : "f"(s))
#define UNPACK2(lo, hi, v) \
    asm("mov.b64 {%0, %1}, %2;" : "=f"(lo), "=f"(hi) : "l"(v))

// ---------------------------------------------------------------------------
// GEMM tiling: BM=BN=128, BK=16, 256 threads, 8x8 micro-tile (as 8x4 f32x2
// pairs along N), double-buffered SMEM.
// ---------------------------------------------------------------------------
#define BKK 16
#define AST 132

// ---------------------------------------------------------------------------
// Kernel 1: fused gather + QKV GEMM.
// ---------------------------------------------------------------------------
__global__ __launch_bounds__(256) void qkv_kernel(
    const float* __restrict__ x,
    const float* __restrict__ w,      // [256, 768]
    const float* __restrict__ bias)   // [768]
{
    __shared__ float As[2][BKK][AST];
    __shared__ float Bs[2][BKK][AST];

    const int tid     = threadIdx.x;
    const int rowBase = blockIdx.x * 128;
    const int colBase = blockIdx.y * 128;

    const int bt   = rowBase >> 12;
    const int rem0 = rowBase & 4095;

    const int a_c  = tid >> 5;
    const int a_m4 = (tid & 31) << 2;
    const int b_c  = tid >> 5;
    const int b_j4 = (tid & 31) << 2;

    const int ty = tid >> 4, tx = tid & 15;
    const int m0 = ty * 8,   n0 = tx * 8;

    unsigned long long acc2[8][4];
    #pragma unroll
    for (int mi = 0; mi < 8; mi++)
        #pragma unroll
        for (int nj = 0; nj < 4; nj++) acc2[mi][nj] = 0ULL;

    float4 a0, a1, b0, b1;
    a0 = *(const float4*)(x + ((size_t)(bt * C_ + a_c)     << 12) + rem0 + a_m4);
    a1 = *(const float4*)(x + ((size_t)(bt * C_ + a_c + 8) << 12) + rem0 + a_m4);
    b0 = *(const float4*)(w + (size_t)(b_c)     * 768 + colBase + b_j4);
    b1 = *(const float4*)(w + (size_t)(b_c + 8) * 768 + colBase + b_j4);
    *(float4*)&As[0][a_c][a_m4]     = a0;
    *(float4*)&As[0][a_c + 8][a_m4] = a1;
    *(float4*)&Bs[0][b_c][b_j4]     = b0;
    *(float4*)&Bs[0][b_c + 8][b_j4] = b1;
    __syncthreads();

    const int NT = C_ / BKK;   // 16
    for (int kt = 0; kt < NT; kt++) {
        const int buf = kt & 1;
        if (kt + 1 < NT) {
            const int kc = (kt + 1) * BKK;
            a0 = *(const float4*)(x + ((size_t)(bt * C_ + kc + a_c)     << 12) + rem0 + a_m4);
            a1 = *(const float4*)(x + ((size_t)(bt * C_ + kc + a_c + 8) << 12) + rem0 + a_m4);
            b0 = *(const float4*)(w + (size_t)(kc + b_c)     * 768 + colBase + b_j4);
            b1 = *(const float4*)(w + (size_t)(kc + b_c + 8) * 768 + colBase + b_j4);
        }
        #pragma unroll
        for (int kk = 0; kk < BKK; kk++) {
            float a[8];
            *(float4*)&a[0] = *(const float4*)&As[buf][kk][m0];
            *(float4*)&a[4] = *(const float4*)&As[buf][kk][m0 + 4];
            ulonglong2 bv0 = *(const ulonglong2*)&Bs[buf][kk][n0];
            ulonglong2 bv1 = *(const ulonglong2*)&Bs[buf][kk][n0 + 4];
            #pragma unroll
            for (int mi = 0; mi < 8; mi++) {
                unsigned long long a2;
                PACK2(a2, a[mi]);
                FMA2(acc2[mi][0], a2, bv0.x);
                FMA2(acc2[mi][1], a2, bv0.y);
                FMA2(acc2[mi][2], a2, bv1.x);
                FMA2(acc2[mi][3], a2, bv1.y);
            }
        }
        if (kt + 1 < NT) {
            const int nb = buf ^ 1;
            *(float4*)&As[nb][a_c][a_m4]     = a0;
            *(float4*)&As[nb][a_c + 8][a_m4] = a1;
            *(float4*)&Bs[nb][b_c][b_j4]     = b0;
            *(float4*)&Bs[nb][b_c + 8][b_j4] = b1;
            __syncthreads();
        }
    }

    // Epilogue: route to q/k/v, packed bias add + 8B stores.
    const int part = colBase >> 8;                  // 0=q, 1=k, 2=v
    float* dst = (part == 0) ? g_q : (part == 1) ? g_k : g_v;
    const int jl0 = (colBase & 255) + n0;

    #pragma unroll
    for (int mi = 0; mi < 8; mi++) {
        const size_t rofs = (size_t)(rowBase + m0 + mi) * C_;
        #pragma unroll
        for (int nj = 0; nj < 4; nj++) {
            unsigned long long bias2 =
                *(const unsigned long long*)&bias[colBase + n0 + 2 * nj];
            unsigned long long r;
            ADD2(r, acc2[mi][nj], bias2);
            *(unsigned long long*)&dst[rofs + jl0 + 2 * nj] = r;
        }
    }
}

// ---------------------------------------------------------------------------
// Kernel 2: attention per (sequence, head-pair); f32x2 in the QK and PV
// loops, softmax unchanged. o overwrites g_q in place.
// ---------------------------------------------------------------------------
__global__ __launch_bounds__(128) void attn_kernel(const float* __restrict__ rb)
{
    __shared__ float ksm[2 * 64 * DH];
    __shared__ float vsm[2 * 64 * DH];

    const int tid  = threadIdx.x;
    const int n    = blockIdx.x;
    const int hp   = blockIdx.y;
    const int hsub = tid >> 6;
    const int i    = tid & 63;
    const int h    = hp * 2 + hsub;

    const size_t base = (size_t)n * 64 * C_;

    #pragma unroll
    for (int it = 0; it < 8; it++) {
        int e   = tid + 128 * it;
        int hs  = e >> 9;
        int row = (e >> 3) & 63;
        int d4  = (e & 7) << 2;
        int hh  = hp * 2 + hs;
        size_t g = base + (size_t)row * C_ + hh * DH + d4;
        ((float4*)ksm)[e] = *(const float4*)&g_k[g];
        ((float4*)vsm)[e] = *(const float4*)&g_v[g];
    }

    // q row -> 16 packed f32x2 pairs
    unsigned long long qv2[16];
    const size_t qbase = base + (size_t)i * C_ + h * DH;
    #pragma unroll
    for (int t = 0; t < 16; t += 2) {
        ulonglong2 p = *(const ulonglong2*)&g_q[qbase + 2 * t];
        qv2[t] = p.x;  qv2[t + 1] = p.y;
    }
    __syncthreads();

    const float* brow  = rb + (size_t)h * 4096 + i * 64;
    const float* kbase = ksm + hsub * (64 * DH);
    float s[64];
    float m = -1e30f;
    #pragma unroll
    for (int j = 0; j < 64; j++) {
        const float* krow = kbase + j * DH;
        unsigned long long dd[4] = {0ULL, 0ULL, 0ULL, 0ULL};
        #pragma unroll
        for (int t = 0; t < 16; t += 2) {
            ulonglong2 kk2 = *(const ulonglong2*)&krow[2 * t];
            FMA2(dd[t & 3],       qv2[t],     kk2.x);
            FMA2(dd[(t + 1) & 3], qv2[t + 1], kk2.y);
        }
        float x0, x1, x2, x3, x4, x5, x6, x7;
        UNPACK2(x0, x1, dd[0]);
        UNPACK2(x2, x3, dd[1]);
        UNPACK2(x4, x5, dd[2]);
        UNPACK2(x6, x7, dd[3]);
        float dot = ((x0 + x1) + (x2 + x3)) + ((x4 + x5) + (x6 + x7));
        float sc = fmaf(dot, SCALE, brow[j]);
        s[j] = sc;
        m = fmaxf(m, sc);
    }

    float sum = 0.f;
    #pragma unroll
    for (int j = 0; j < 64; j++) {
        float e = __expf(s[j] - m);
        s[j] = e;
        sum += e;
    }
    const float inv = 1.f / sum;

    unsigned long long o2[16];
    #pragma unroll
    for (int t = 0; t < 16; t++) o2[t] = 0ULL;
    const float* vbase = vsm + hsub * (64 * DH);
    #pragma unroll
    for (int j = 0; j < 64; j++) {
        float p = s[j] * inv;
        unsigned long long pp;
        PACK2(pp, p);
        const float* vrow = vbase + j * DH;
        #pragma unroll
        for (int t = 0; t < 16; t += 2) {
            ulonglong2 vv = *(const ulonglong2*)&vrow[2 * t];
            FMA2(o2[t],     pp, vv.x);
            FMA2(o2[t + 1], pp, vv.y);
        }
    }

    #pragma unroll
    for (int t = 0; t < 16; t += 2) {
        ulonglong2 p;
        p.x = o2[t]; p.y = o2[t + 1];
        *(ulonglong2*)&g_q[qbase + 2 * t] = p;
    }
}

// ---------------------------------------------------------------------------
// Kernel 3: output projection + scatter, BK=16 double-buffered, f32x2 core.
// ---------------------------------------------------------------------------
__global__ __launch_bounds__(256) void proj_kernel(
    const float* __restrict__ w,      // [256, 256]
    const float* __restrict__ bias,   // [256]
    float* __restrict__ out)
{
    __shared__ float As[2][BKK][AST];
    __shared__ float Bs[2][BKK][AST];

    const int tid     = threadIdx.x;
    const int rowBase = blockIdx.x * 128;
    const int colBase = blockIdx.y * 128;

    const int a_m  = tid >> 2;             // 0..63
    const int a_k4 = (tid & 3) << 2;       // 0,4,8,12
    const int b_c  = tid >> 5;
    const int b_j4 = (tid & 31) << 2;

    const int ty = tid >> 4, tx = tid & 15;
    const int m0 = ty * 8,   n0 = tx * 8;

    unsigned long long acc2[8][4];
    #pragma unroll
    for (int mi = 0; mi < 8; mi++)
        #pragma unroll
        for (int nj = 0; nj < 4; nj++) acc2[mi][nj] = 0ULL;

    float4 a0, a1, b0, b1;
    a0 = *(const float4*)(g_q + (size_t)(rowBase + a_m)      * C_ + a_k4);
    a1 = *(const float4*)(g_q + (size_t)(rowBase + a_m + 64) * C_ + a_k4);
    b0 = *(const float4*)(w + (size_t)(b_c)     * C_ + colBase + b_j4);
    b1 = *(const float4*)(w + (size_t)(b_c + 8) * C_ + colBase + b_j4);
    As[0][a_k4+0][a_m] = a0.x; As[0][a_k4+1][a_m] = a0.y;
    As[0][a_k4+2][a_m] = a0.z; As[0][a_k4+3][a_m] = a0.w;
    As[0][a_k4+0][a_m+64] = a1.x; As[0][a_k4+1][a_m+64] = a1.y;
    As[0][a_k4+2][a_m+64] = a1.z; As[0][a_k4+3][a_m+64] = a1.w;
    *(float4*)&Bs[0][b_c][b_j4]     = b0;
    *(float4*)&Bs[0][b_c + 8][b_j4] = b1;
    __syncthreads();

    const int NT = C_ / BKK;   // 16
    for (int kt = 0; kt < NT; kt++) {
        const int buf = kt & 1;
        if (kt + 1 < NT) {
            const int kc = (kt + 1) * BKK;
            a0 = *(const float4*)(g_q + (size_t)(rowBase + a_m)      * C_ + kc + a_k4);
            a1 = *(const float4*)(g_q + (size_t)(rowBase + a_m + 64) * C_ + kc + a_k4);
            b0 = *(const float4*)(w + (size_t)(kc + b_c)     * C_ + colBase + b_j4);
            b1 = *(const float4*)(w + (size_t)(kc + b_c + 8) * C_ + colBase + b_j4);
        }
        #pragma unroll
        for (int kk = 0; kk < BKK; kk++) {
            float a[8];
            *(float4*)&a[0] = *(const float4*)&As[buf][kk][m0];
            *(float4*)&a[4] = *(const float4*)&As[buf][kk][m0 + 4];
            ulonglong2 bv0 = *(const ulonglong2*)&Bs[buf][kk][n0];
            ulonglong2 bv1 = *(const ulonglong2*)&Bs[buf][kk][n0 + 4];
            #pragma unroll
            for (int mi = 0; mi < 8; mi++) {
                unsigned long long a2;
                PACK2(a2, a[mi]);
                FMA2(acc2[mi][0], a2, bv0.x);
                FMA2(acc2[mi][1], a2, bv0.y);
                FMA2(acc2[mi][2], a2, bv1.x);
                FMA2(acc2[mi][3], a2, bv1.y);
            }
        }
        if (kt + 1 < NT) {
            const int nb = buf ^ 1;
            As[nb][a_k4+0][a_m] = a0.x; As[nb][a_k4+1][a_m] = a0.y;
            As[nb][a_k4+2][a_m] = a0.z; As[nb][a_k4+3][a_m] = a0.w;
            As[nb][a_k4+0][a_m+64] = a1.x; As[nb][a_k4+1][a_m+64] = a1.y;
            As[nb][a_k4+2][a_m+64] = a1.z; As[nb][a_k4+3][a_m+64] = a1.w;
            *(float4*)&Bs[nb][b_c][b_j4]     = b0;
            *(float4*)&Bs[nb][b_c + 8][b_j4] = b1;
            __syncthreads();
        }
    }

    // Scatter epilogue: out[(bt*C + c_out)*4096 + rem]  (unpack pairs)
    const int bt = rowBase >> 12;
    #pragma unroll
    for (int mi = 0; mi < 8; mi++) {
        const int r   = rowBase + m0 + mi;
        const int rem = r & 4095;
        #pragma unroll
        for (int nj = 0; nj < 4; nj++) {
            const int c_out = colBase + n0 + 2 * nj;
            float lo, hi;
            UNPACK2(lo, hi, acc2[mi][nj]);
            out[((size_t)(bt * C_ + c_out)     << 12) + rem] = lo + bias[c_out];
            out[((size_t)(bt * C_ + c_out + 1) << 12) + rem] = hi + bias[c_out + 1];
        }
    }
}

// ---------------------------------------------------------------------------
extern "C" void kernel_launch(void* const* d_in, const int* in_sizes, int n_in,
                              void* d_out, int out_size)
{
    const float* x      = (const float*)d_in[0];
    const float* rb     = (const float*)d_in[1];
    const float* w_qkv  = (const float*)d_in[2];
    const float* b_qkv  = (const float*)d_in[3];
    const float* w_proj = (const float*)d_in[4];
    const float* b_proj = (const float*)d_in[5];
    float* out = (float*)d_out;
    (void)in_sizes; (void)n_in; (void)out_size;

    qkv_kernel<<<dim3(NTOK / 128, 6), 256>>>(x, w_qkv, b_qkv);
    attn_kernel<<<dim3(NSEQ, HEADS / 2), 128>>>(rb);
    proj_kernel<<<dim3(NTOK / 128, 2), 256>>>(w_proj, b_proj, out);
}